// round 1
// baseline (speedup 1.0000x reference)
#include <cuda_runtime.h>
#include <math.h>

// Problem constants (fixed by the reference)
#define B_N 8192
#define D_N 512
#define K_N 20
#define NSEG 32          // column segments (top-k computed per segment, merged later)
#define CT_PER_SEG 2     // 64 column tiles / 32 segments
#define BM 128
#define BN 128
#define BKC 16
#define LDT 132          // padded smem row stride for A/B tiles (floats)
#define LDC 129          // padded smem row stride for C dump (floats)

// Scratch (allocation-free: __device__ globals)
__device__ float g_xn[B_N * D_N];                 // normalized rows, 16.8 MB (L2-resident)
__device__ float g_pvals[B_N * NSEG * K_N];       // partial top-k values
__device__ int   g_pidx [B_N * NSEG * K_N];       // partial top-k indices
__device__ float g_rowloss[B_N];                  // per-row BCE sums

// ---------------------------------------------------------------------------
// 1) Row L2 normalization: xn = x / max(||x||, 1e-12)
// ---------------------------------------------------------------------------
__global__ void normalize_kernel(const float* __restrict__ x) {
    __shared__ float warp_ss[4];
    __shared__ float s_inv;
    int row = blockIdx.x;
    int t = threadIdx.x;  // 128 threads
    const float* xr = x + row * D_N;
    float v[4];
    float ss = 0.f;
#pragma unroll
    for (int i = 0; i < 4; i++) { v[i] = xr[t + 128 * i]; ss += v[i] * v[i]; }
#pragma unroll
    for (int off = 16; off > 0; off >>= 1) ss += __shfl_xor_sync(0xffffffffu, ss, off);
    if ((t & 31) == 0) warp_ss[t >> 5] = ss;
    __syncthreads();
    if (t == 0) {
        float tot = warp_ss[0] + warp_ss[1] + warp_ss[2] + warp_ss[3];
        s_inv = 1.0f / fmaxf(sqrtf(tot), 1e-12f);
    }
    __syncthreads();
    float inv = s_inv;
#pragma unroll
    for (int i = 0; i < 4; i++) g_xn[row * D_N + t + 128 * i] = v[i] * inv;
}

// ---------------------------------------------------------------------------
// 2) Fused cosine GEMM + per-row top-20 (per column segment)
//    Block: 256 threads, C tile 128x128, K-chunk 16, 8x8 micro-tile (4+4 split)
// ---------------------------------------------------------------------------
extern __shared__ float smem[];

__global__ __launch_bounds__(256, 2) void gemm_topk_kernel() {
    float* As  = smem;                    // [BKC][LDT]
    float* Bs  = smem + BKC * LDT;        // [BKC][LDT]
    float* Csh = Bs + BKC * LDT;          // [BM][LDC]

    const int tid = threadIdx.x;
    const int tx = tid & 15;
    const int ty = tid >> 4;
    const int rowBase = blockIdx.x * BM;  // 64 row tiles
    const int seg = blockIdx.y;           // 32 segments

    // staging-load mapping: thread -> (row, 8 consecutive k)
    const int ldrow = tid >> 1;           // 0..127
    const int kb = (tid & 1) << 3;        // 0 or 8
    const float* Aptr = g_xn + (size_t)(rowBase + ldrow) * D_N + kb;

    float topv[K_N];
    int   topi[K_N];
#pragma unroll
    for (int q = 0; q < K_N; q++) { topv[q] = -2.0f; topi[q] = 0; }

    for (int ct = 0; ct < CT_PER_SEG; ct++) {
        const int colBase = (seg * CT_PER_SEG + ct) * BN;
        const float* Bptr = g_xn + (size_t)(colBase + ldrow) * D_N + kb;

        float acc[8][8];
#pragma unroll
        for (int r = 0; r < 8; r++)
#pragma unroll
            for (int c = 0; c < 8; c++) acc[r][c] = 0.f;

        // prefetch chunk 0 into registers
        float4 pa0 = *(const float4*)(Aptr);
        float4 pa1 = *(const float4*)(Aptr + 4);
        float4 pb0 = *(const float4*)(Bptr);
        float4 pb1 = *(const float4*)(Bptr + 4);

        for (int kc = 0; kc < D_N / BKC; kc++) {
            __syncthreads();
            // stage (transposed) into shared
            As[(kb + 0) * LDT + ldrow] = pa0.x;
            As[(kb + 1) * LDT + ldrow] = pa0.y;
            As[(kb + 2) * LDT + ldrow] = pa0.z;
            As[(kb + 3) * LDT + ldrow] = pa0.w;
            As[(kb + 4) * LDT + ldrow] = pa1.x;
            As[(kb + 5) * LDT + ldrow] = pa1.y;
            As[(kb + 6) * LDT + ldrow] = pa1.z;
            As[(kb + 7) * LDT + ldrow] = pa1.w;
            Bs[(kb + 0) * LDT + ldrow] = pb0.x;
            Bs[(kb + 1) * LDT + ldrow] = pb0.y;
            Bs[(kb + 2) * LDT + ldrow] = pb0.z;
            Bs[(kb + 3) * LDT + ldrow] = pb0.w;
            Bs[(kb + 4) * LDT + ldrow] = pb1.x;
            Bs[(kb + 5) * LDT + ldrow] = pb1.y;
            Bs[(kb + 6) * LDT + ldrow] = pb1.z;
            Bs[(kb + 7) * LDT + ldrow] = pb1.w;
            __syncthreads();

            if (kc + 1 < D_N / BKC) {  // prefetch next chunk
                int off = (kc + 1) * BKC;
                pa0 = *(const float4*)(Aptr + off);
                pa1 = *(const float4*)(Aptr + off + 4);
                pb0 = *(const float4*)(Bptr + off);
                pb1 = *(const float4*)(Bptr + off + 4);
            }

#pragma unroll
            for (int k = 0; k < BKC; k++) {
                float a[8], b[8];
                *(float4*)&a[0] = *(const float4*)&As[k * LDT + ty * 4];
                *(float4*)&a[4] = *(const float4*)&As[k * LDT + 64 + ty * 4];
                *(float4*)&b[0] = *(const float4*)&Bs[k * LDT + tx * 4];
                *(float4*)&b[4] = *(const float4*)&Bs[k * LDT + 64 + tx * 4];
#pragma unroll
                for (int r = 0; r < 8; r++)
#pragma unroll
                    for (int c = 0; c < 8; c++)
                        acc[r][c] = fmaf(a[r], b[c], acc[r][c]);
            }
        }

        // dump C tile to shared
#pragma unroll
        for (int r = 0; r < 8; r++) {
            int grow = (r >> 2) * 64 + ty * 4 + (r & 3);
#pragma unroll
            for (int c = 0; c < 8; c++) {
                int gcol = (c >> 2) * 64 + tx * 4 + (c & 3);
                Csh[grow * LDC + gcol] = acc[r][c];
            }
        }
        __syncthreads();

        // per-row top-k update (one thread per row; diagonal excluded)
        if (tid < BM) {
            const int gi = rowBase + tid;
            float th = topv[K_N - 1];
            const float* crow = Csh + tid * LDC;
            for (int c = 0; c < BN; c++) {
                float v = crow[c];
                int gj = colBase + c;
                if (v > th && gj != gi) {
                    int p = K_N - 1;
                    while (p > 0 && topv[p - 1] < v) {
                        topv[p] = topv[p - 1];
                        topi[p] = topi[p - 1];
                        p--;
                    }
                    topv[p] = v;
                    topi[p] = gj;
                    th = topv[K_N - 1];
                }
            }
        }
        // next tile's first __syncthreads protects Csh reuse
    }

    if (tid < BM) {
        int gi = rowBase + tid;
        float* pv = g_pvals + ((size_t)gi * NSEG + seg) * K_N;
        int*   pi = g_pidx  + ((size_t)gi * NSEG + seg) * K_N;
#pragma unroll
        for (int q = 0; q < K_N; q++) { pv[q] = topv[q]; pi[q] = topi[q]; }
    }
}

// ---------------------------------------------------------------------------
// 3) Merge partial top-k lists per row + BCE row sums
// ---------------------------------------------------------------------------
__global__ void merge_loss_kernel(const int* __restrict__ labels) {
    int row = blockIdx.x * blockDim.x + threadIdx.x;
    if (row >= B_N) return;
    float tv[K_N];
    int   ti[K_N];
#pragma unroll
    for (int q = 0; q < K_N; q++) { tv[q] = -2.0f; ti[q] = 0; }
    const float* pv = g_pvals + (size_t)row * NSEG * K_N;
    const int*   pi = g_pidx  + (size_t)row * NSEG * K_N;
    float th = -2.0f;
    for (int s = 0; s < NSEG; s++) {
        for (int q = 0; q < K_N; q++) {
            float v = pv[s * K_N + q];
            if (v <= th) break;  // segment lists are descending
            int idx = pi[s * K_N + q];
            int p = K_N - 1;
            while (p > 0 && tv[p - 1] < v) {
                tv[p] = tv[p - 1];
                ti[p] = ti[p - 1];
                p--;
            }
            tv[p] = v;
            ti[p] = idx;
            th = tv[K_N - 1];
        }
    }
    int lab = labels[row];
    float sum = 0.f;
#pragma unroll
    for (int q = 0; q < K_N; q++) {
        float pred = 0.5f * (tv[q] + 1.0f);
        float logp   = fmaxf(logf(pred), -100.0f);
        float log1mp = fmaxf(log1pf(-pred), -100.0f);
        sum += (labels[ti[q]] == lab) ? -logp : -log1mp;
    }
    g_rowloss[row] = sum;
}

// ---------------------------------------------------------------------------
// 4) Deterministic final reduction: mean over B*K terms
// ---------------------------------------------------------------------------
__global__ void reduce_kernel(float* __restrict__ out) {
    __shared__ double sh[256];
    double s = 0.0;
    for (int i = threadIdx.x; i < B_N; i += 256) s += (double)g_rowloss[i];
    sh[threadIdx.x] = s;
    __syncthreads();
    for (int off = 128; off > 0; off >>= 1) {
        if (threadIdx.x < off) sh[threadIdx.x] += sh[threadIdx.x + off];
        __syncthreads();
    }
    if (threadIdx.x == 0) out[0] = (float)(sh[0] / (double)((long long)B_N * K_N));
}

// ---------------------------------------------------------------------------
extern "C" void kernel_launch(void* const* d_in, const int* in_sizes, int n_in,
                              void* d_out, int out_size) {
    const float* batch  = (const float*)d_in[0];
    const int*   labels = (const int*)d_in[1];
    float* out = (float*)d_out;
    (void)in_sizes; (void)n_in; (void)out_size;

    const size_t smem_bytes = (size_t)(2 * BKC * LDT + BM * LDC) * sizeof(float); // 82944
    cudaFuncSetAttribute(gemm_topk_kernel,
                         cudaFuncAttributeMaxDynamicSharedMemorySize,
                         (int)smem_bytes);

    normalize_kernel<<<B_N, 128>>>(batch);
    dim3 g(B_N / BM, NSEG);
    gemm_topk_kernel<<<g, 256, smem_bytes>>>();
    merge_loss_kernel<<<B_N / 128, 128>>>(labels);
    reduce_kernel<<<1, 256>>>(out);
}

// round 3
// speedup vs baseline: 2.5957x; 2.5957x over previous
#include <cuda_runtime.h>
#include <cuda_bf16.h>
#include <math.h>
#include <stdint.h>

// ---------------------------------------------------------------------------
// Problem constants
// ---------------------------------------------------------------------------
#define B_N 8192
#define D_N 512
#define K_N 20

// GEMM tiling
#define BM 128
#define BNC 128               // cols per CTA
#define CK 64                 // K elems per chunk (64 bf16 = 128B row)
#define NC (D_N / CK)         // 8 chunks
#define NSEG (B_N / BNC)      // 64 column segments
#define LDC 129

#define STG_A 16384           // 128*64*2 bytes
#define STG_BUF 32768         // A+B per buffer
#define SMEM_BYTES 66048      // max(2*STG_BUF=65536, 128*129*4=66048)

// ---------------------------------------------------------------------------
// Scratch (__device__ globals — allocation-free)
// ---------------------------------------------------------------------------
__device__ __align__(128) __nv_bfloat16 g_xb[B_N * D_N];   // normalized rows (bf16)
__device__ float g_pvals[(size_t)B_N * NSEG * K_N];
__device__ int   g_pidx [(size_t)B_N * NSEG * K_N];
__device__ float g_blocksum[B_N / 128];

// ---------------------------------------------------------------------------
// PTX helpers (baseline ISA only: cp.async, ldmatrix, mma.sync — no "a" features)
// ---------------------------------------------------------------------------
__device__ __forceinline__ uint32_t smem_u32(const void* p) {
    uint32_t a;
    asm("{ .reg .u64 t; cvta.to.shared.u64 t, %1; cvt.u32.u64 %0, t; }" : "=r"(a) : "l"(p));
    return a;
}

__device__ __forceinline__ void cp_async16(uint32_t dst, const void* src) {
    asm volatile("cp.async.cg.shared.global [%0], [%1], 16;" :: "r"(dst), "l"(src) : "memory");
}
#define CP_COMMIT() asm volatile("cp.async.commit_group;" ::: "memory")
#define CP_WAIT1()  asm volatile("cp.async.wait_group 1;" ::: "memory")
#define CP_WAIT0()  asm volatile("cp.async.wait_group 0;" ::: "memory")

#define LDSM_X4(r0, r1, r2, r3, addr)                                        \
    asm volatile("ldmatrix.sync.aligned.m8n8.x4.shared.b16 {%0,%1,%2,%3}, [%4];" \
                 : "=r"(r0), "=r"(r1), "=r"(r2), "=r"(r3) : "r"(addr))

__device__ __forceinline__ void mma16816(float* c, uint32_t a0, uint32_t a1,
                                         uint32_t a2, uint32_t a3,
                                         uint32_t b0, uint32_t b1) {
    asm volatile(
        "mma.sync.aligned.m16n8k16.row.col.f32.bf16.bf16.f32 "
        "{%0,%1,%2,%3}, {%4,%5,%6,%7}, {%8,%9}, {%0,%1,%2,%3};"
        : "+f"(c[0]), "+f"(c[1]), "+f"(c[2]), "+f"(c[3])
        : "r"(a0), "r"(a1), "r"(a2), "r"(a3), "r"(b0), "r"(b1));
}

// ---------------------------------------------------------------------------
// 1) Row L2 normalization -> bf16
// ---------------------------------------------------------------------------
__global__ void normalize_kernel(const float* __restrict__ x) {
    __shared__ float warp_ss[4];
    __shared__ float s_inv;
    int row = blockIdx.x;
    int t = threadIdx.x;  // 128
    const float* xr = x + row * D_N;
    float v[4];
    float ss = 0.f;
#pragma unroll
    for (int i = 0; i < 4; i++) { v[i] = xr[t + 128 * i]; ss += v[i] * v[i]; }
#pragma unroll
    for (int off = 16; off > 0; off >>= 1) ss += __shfl_xor_sync(0xffffffffu, ss, off);
    if ((t & 31) == 0) warp_ss[t >> 5] = ss;
    __syncthreads();
    if (t == 0) {
        float tot = warp_ss[0] + warp_ss[1] + warp_ss[2] + warp_ss[3];
        s_inv = 1.0f / fmaxf(sqrtf(tot), 1e-12f);
    }
    __syncthreads();
    float inv = s_inv;
#pragma unroll
    for (int i = 0; i < 4; i++)
        g_xb[row * D_N + t + 128 * i] = __float2bfloat16_rn(v[i] * inv);
}

// ---------------------------------------------------------------------------
// 2) bf16 mma.sync GEMM (128x128 x 512) + fused per-row top-20 epilogue
//    256 threads = 8 warps, warp tile 64x32 (4x4 m16n8k16)
// ---------------------------------------------------------------------------
extern __shared__ char smem_raw[];

__global__ __launch_bounds__(256, 2) void gemm_topk_mma() {
    const int tid = threadIdx.x;
    const int lane = tid & 31;
    const int wid = tid >> 5;
    const int wm = wid & 1;        // 0,1 -> M offset 0/64
    const int wn = wid >> 1;       // 0..3 -> N offset 0/32/64/96
    const int rowBase = blockIdx.y * BM;
    const int colBase = blockIdx.x * BNC;

    const uint32_t sbase = smem_u32(smem_raw);
    float* Csh = (float*)smem_raw;

    // --- cp.async staging (per-thread: 4 16B chunks for A, 4 for B per k-chunk)
    // chunk id cid = tid + 256*i : row = cid>>3 (0..127), c16 = cid&7
    // smem off = row*128 + ((c16*16) ^ ((row&7)<<4))   [SW128 swizzle, cb<128]
    uint32_t soff[4];
    uint32_t grow[4];
#pragma unroll
    for (int i = 0; i < 4; i++) {
        int cid = tid + 256 * i;
        int r = cid >> 3, c16 = cid & 7;
        soff[i] = (uint32_t)(r * 128 + ((c16 * 16) ^ ((r & 7) << 4)));
        grow[i] = (uint32_t)(r * (D_N * 2) + c16 * 16);  // byte offset within tile rows
    }
    const char* Agbase = (const char*)g_xb + (size_t)rowBase * D_N * 2;
    const char* Bgbase = (const char*)g_xb + (size_t)colBase * D_N * 2;

    // --- ldmatrix per-lane row addressing (precomputed swizzle pieces)
    // A m-tile mt: r = wm*64 + mt*16 + (lane&7) + ((lane>>3)&1)*8 ; khalf=(lane>>4)
    // B n-pair np: r = wn*32 + np*16 + (lane&7) + (lane>>4)*8     ; khalf=((lane>>3)&1)
    const uint32_t rx = (uint32_t)((lane & 7) << 4);   // swizzle xor term (r&7 == lane&7)
    const uint32_t ah = (uint32_t)((lane >> 4) << 4);  // A k-half byte
    const uint32_t bh = (uint32_t)(((lane >> 3) & 1) << 4);
    uint32_t arow[4], brow[2];
#pragma unroll
    for (int mt = 0; mt < 4; mt++)
        arow[mt] = (uint32_t)((wm * 64 + mt * 16 + (lane & 7) + ((lane >> 3) & 1) * 8) * 128);
#pragma unroll
    for (int np = 0; np < 2; np++)
        brow[np] = (uint32_t)((wn * 32 + np * 16 + (lane & 7) + (lane >> 4) * 8) * 128);

    float acc[4][4][4];
#pragma unroll
    for (int mt = 0; mt < 4; mt++)
#pragma unroll
        for (int nt = 0; nt < 4; nt++)
#pragma unroll
            for (int q = 0; q < 4; q++) acc[mt][nt][q] = 0.f;

    // --- prologue: stage chunks 0 and 1
#pragma unroll
    for (int pc = 0; pc < 2; pc++) {
        uint32_t ab = sbase + pc * STG_BUF;
        uint32_t bb = ab + STG_A;
        const char* Ag = Agbase + pc * (CK * 2);
        const char* Bg = Bgbase + pc * (CK * 2);
#pragma unroll
        for (int i = 0; i < 4; i++) {
            cp_async16(ab + soff[i], Ag + grow[i]);
            cp_async16(bb + soff[i], Bg + grow[i]);
        }
        CP_COMMIT();
    }

    for (int kc = 0; kc < NC; kc++) {
        if (kc == NC - 1) CP_WAIT0(); else CP_WAIT1();
        __syncthreads();

        const uint32_t ab = sbase + (kc & 1) * STG_BUF;
        const uint32_t bb = ab + STG_A;
#pragma unroll
        for (int ks = 0; ks < 4; ks++) {
            const uint32_t kbyte = (uint32_t)(ks * 32);
            uint32_t a[4][4], b[2][4];
#pragma unroll
            for (int mt = 0; mt < 4; mt++)
                LDSM_X4(a[mt][0], a[mt][1], a[mt][2], a[mt][3],
                        ab + arow[mt] + ((kbyte + ah) ^ rx));
#pragma unroll
            for (int np = 0; np < 2; np++)
                LDSM_X4(b[np][0], b[np][1], b[np][2], b[np][3],
                        bb + brow[np] + ((kbyte + bh) ^ rx));
#pragma unroll
            for (int mt = 0; mt < 4; mt++)
#pragma unroll
                for (int nt = 0; nt < 4; nt++)
                    mma16816(acc[mt][nt],
                             a[mt][0], a[mt][1], a[mt][2], a[mt][3],
                             b[nt >> 1][2 * (nt & 1)], b[nt >> 1][2 * (nt & 1) + 1]);
        }
        __syncthreads();

        if (kc + 2 < NC) {
            uint32_t ab2 = sbase + (kc & 1) * STG_BUF;
            uint32_t bb2 = ab2 + STG_A;
            const char* Ag = Agbase + (kc + 2) * (CK * 2);
            const char* Bg = Bgbase + (kc + 2) * (CK * 2);
#pragma unroll
            for (int i = 0; i < 4; i++) {
                cp_async16(ab2 + soff[i], Ag + grow[i]);
                cp_async16(bb2 + soff[i], Bg + grow[i]);
            }
            CP_COMMIT();
        }
    }
    __syncthreads();  // all smem reads done before Csh overwrite

    // --- dump accumulators to Csh
    {
        const int g = lane >> 2;
        const int c2 = 2 * (lane & 3);
#pragma unroll
        for (int mt = 0; mt < 4; mt++) {
            const int r0 = wm * 64 + mt * 16 + g;
#pragma unroll
            for (int nt = 0; nt < 4; nt++) {
                const int c0 = wn * 32 + nt * 8 + c2;
                Csh[r0 * LDC + c0]           = acc[mt][nt][0];
                Csh[r0 * LDC + c0 + 1]       = acc[mt][nt][1];
                Csh[(r0 + 8) * LDC + c0]     = acc[mt][nt][2];
                Csh[(r0 + 8) * LDC + c0 + 1] = acc[mt][nt][3];
            }
        }
    }
    __syncthreads();

    // --- per-row top-20 (threads 0..127, one row each; diagonal excluded)
    if (tid < BM) {
        float topv[K_N];
        int   topi[K_N];
#pragma unroll
        for (int q = 0; q < K_N; q++) { topv[q] = -2.0f; topi[q] = 0; }
        const int gi = rowBase + tid;
        float th = -2.0f;
        const float* crow = Csh + tid * LDC;
        for (int c = 0; c < BNC; c++) {
            float v = crow[c];
            int gj = colBase + c;
            if (v > th && gj != gi) {
                int p = K_N - 1;
                while (p > 0 && topv[p - 1] < v) {
                    topv[p] = topv[p - 1];
                    topi[p] = topi[p - 1];
                    p--;
                }
                topv[p] = v;
                topi[p] = gj;
                th = topv[K_N - 1];
            }
        }
        float* pv = g_pvals + ((size_t)gi * NSEG + blockIdx.x) * K_N;
        int*   pi = g_pidx  + ((size_t)gi * NSEG + blockIdx.x) * K_N;
#pragma unroll
        for (int q = 0; q < K_N; q++) { pv[q] = topv[q]; pi[q] = topi[q]; }
    }
}

// ---------------------------------------------------------------------------
// 3) Merge 64 partial top-20 lists per row + BCE; block partial sums
// ---------------------------------------------------------------------------
__global__ void merge_loss_kernel(const int* __restrict__ labels) {
    __shared__ float sh[128];
    int row = blockIdx.x * 128 + threadIdx.x;
    float tv[K_N];
    int   ti[K_N];
#pragma unroll
    for (int q = 0; q < K_N; q++) { tv[q] = -2.0f; ti[q] = 0; }
    const float* pv = g_pvals + (size_t)row * NSEG * K_N;
    const int*   pi = g_pidx  + (size_t)row * NSEG * K_N;
    float th = -2.0f;
    for (int s = 0; s < NSEG; s++) {
        for (int q = 0; q < K_N; q++) {
            float v = pv[s * K_N + q];
            if (v <= th) break;  // segment lists are descending
            int idx = pi[s * K_N + q];
            int p = K_N - 1;
            while (p > 0 && tv[p - 1] < v) {
                tv[p] = tv[p - 1];
                ti[p] = ti[p - 1];
                p--;
            }
            tv[p] = v;
            ti[p] = idx;
            th = tv[K_N - 1];
        }
    }
    int lab = labels[row];
    float sum = 0.f;
#pragma unroll
    for (int q = 0; q < K_N; q++) {
        float pred = 0.5f * (tv[q] + 1.0f);
        float logp   = fmaxf(logf(pred), -100.0f);
        float log1mp = fmaxf(log1pf(-pred), -100.0f);
        sum += (labels[ti[q]] == lab) ? -logp : -log1mp;
    }
    sh[threadIdx.x] = sum;
    __syncthreads();
    for (int off = 64; off > 0; off >>= 1) {
        if (threadIdx.x < off) sh[threadIdx.x] += sh[threadIdx.x + off];
        __syncthreads();
    }
    if (threadIdx.x == 0) g_blocksum[blockIdx.x] = sh[0];
}

// ---------------------------------------------------------------------------
// 4) Deterministic final reduction over 64 block sums
// ---------------------------------------------------------------------------
__global__ void reduce_kernel(float* __restrict__ out) {
    __shared__ double sh[64];
    int t = threadIdx.x;
    sh[t] = (double)g_blocksum[t];
    __syncthreads();
    for (int off = 32; off > 0; off >>= 1) {
        if (t < off) sh[t] += sh[t + off];
        __syncthreads();
    }
    if (t == 0) out[0] = (float)(sh[0] / (double)((long long)B_N * K_N));
}

// ---------------------------------------------------------------------------
extern "C" void kernel_launch(void* const* d_in, const int* in_sizes, int n_in,
                              void* d_out, int out_size) {
    const float* batch  = (const float*)d_in[0];
    const int*   labels = (const int*)d_in[1];
    float* out = (float*)d_out;
    (void)in_sizes; (void)n_in; (void)out_size;

    cudaFuncSetAttribute(gemm_topk_mma, cudaFuncAttributeMaxDynamicSharedMemorySize,
                         SMEM_BYTES);

    normalize_kernel<<<B_N, 128>>>(batch);
    dim3 g(NSEG, B_N / BM);  // (64, 64)
    gemm_topk_mma<<<g, 256, SMEM_BYTES>>>();
    merge_loss_kernel<<<B_N / 128, 128>>>(labels);
    reduce_kernel<<<1, 64>>>(out);
}